// round 14
// baseline (speedup 1.0000x reference)
#include <cuda_runtime.h>
#include <cuda_fp16.h>
#include <cuda_fp8.h>
#include <math.h>

#define BB 8
#define CC 16
#define PAIRS (CC/2)
#define QUADS (CC/4)
#define HH 240
#define WW 320
#define NN (HH*WW)
#define ITER_BLOCKS (NN/2/256*BB)   // 150*8 = 1200

// ---------------- device-global state (no allocations allowed) ----------------
__device__ float g_R[BB][9];
__device__ float g_t[BB][3];
__device__ float g_acc[BB][27];            // 21 upper-tri JtWJ + 6 Rhs
__device__ unsigned int g_count;           // last-block counter (zero at load; reset after use)
// g_cen4 : pair-plane-major (b,pair,p): uint2{ fp8x4{a0,a1,g0,g1}, fp8x4{x00,x01,s00,s01} }
// g_gathq: quad-plane-major (b,quad,p): uint2{ fp8x4{x1 c0..c3}, fp8x4{s1 c0..c3} }
__device__ uint2 g_cen4[BB*PAIRS*NN];
__device__ uint2 g_gathq[BB*QUADS*NN];

__device__ __forceinline__ unsigned pack_fp8x4(float a, float b, float c, float d) {
    __nv_fp8x2_storage_t lo = __nv_cvt_float2_to_fp8x2(make_float2(a, b), __NV_SATFINITE, __NV_E4M3);
    __nv_fp8x2_storage_t hi = __nv_cvt_float2_to_fp8x2(make_float2(c, d), __NV_SATFINITE, __NV_E4M3);
    return (unsigned)lo | ((unsigned)hi << 16);
}
__device__ __forceinline__ unsigned short pack_fp8x2(float a, float b) {
    return (unsigned short)__nv_cvt_float2_to_fp8x2(make_float2(a, b), __NV_SATFINITE, __NV_E4M3);
}
__device__ __forceinline__ __half2 fp8x2_to_h2(unsigned short v) {
    __half2_raw r = __nv_cvt_fp8x2_to_halfraw2((__nv_fp8x2_storage_t)v, __NV_E4M3);
    return *(__half2*)&r;
}

__device__ __forceinline__ void rodrigues(float wx, float wy, float wz, float* R) {
    float th = sqrtf(wx*wx + wy*wy + wz*wz) + 1e-12f;
    float inv = 1.0f / th;
    float ax = wx*inv, ay = wy*inv, az = wz*inv;
    float s = sinf(th), c = cosf(th), mc = 1.0f - c;
    R[0] = c + mc*ax*ax;     R[1] = mc*ax*ay - s*az;  R[2] = mc*ax*az + s*ay;
    R[3] = mc*ax*ay + s*az;  R[4] = c + mc*ay*ay;     R[5] = mc*ay*az - s*ax;
    R[6] = mc*ax*az - s*ay;  R[7] = mc*ay*az + s*ax;  R[8] = c + mc*az*az;
}

// ---------------- pack: sobel + fp8 layouts (pair cen, quad gather); init fused ----------------
__global__ __launch_bounds__(256)
void packKernel(const float* __restrict__ twist0, const float* __restrict__ x0,
                const float* __restrict__ sigma0, const float* __restrict__ x1,
                const float* __restrict__ sigma1) {
    if (blockIdx.x == 0 && threadIdx.x < BB) {      // fused init
        int b = threadIdx.x;
        rodrigues(twist0[b*6+0], twist0[b*6+1], twist0[b*6+2], g_R[b]);
        g_t[b][0] = twist0[b*6+3];
        g_t[b][1] = twist0[b*6+4];
        g_t[b][2] = twist0[b*6+5];
#pragma unroll
        for (int k = 0; k < 27; k++) g_acc[b][k] = 0.0f;
    }

    int t = blockIdx.x * 256 + threadIdx.x;         // one thread = 4 pixels, one channel-quad
    int nPix4 = NN / 4;
    int p4  = (t % nPix4) * 4;
    int bq  = t / nPix4;                             // 0..BB*QUADS-1
    int b    = bq >> 2;
    int quad = bq & 3;
    int v  = p4 / WW;
    int u0 = p4 - v*WW;                              // %4==0, row-contained

    int vm = max(v-1, 0)*WW, v0r = v*WW, vp = min(v+1, HH-1)*WW;
    int ul = max(u0-1, 0);
    int ur = min(u0+4, WW-1);

    unsigned agw[2][4], xsw[2][4];
    unsigned short x1p[2][4], s1p[2][4];
#pragma unroll
    for (int pair = 0; pair < 2; pair++) {
        float av[2][4], gv[2][4], x0a[2][4], s0a[2][4], x1a[2][4], s1a[2][4];
#pragma unroll
        for (int ch = 0; ch < 2; ch++) {
            int c = quad*4 + pair*2 + ch;
            size_t off = (size_t)(b*CC + c)*NN;
            const float* img = x0 + off;

            float top[6], mid[6], bot[6];
            float4 q;
            q = *(const float4*)(img + vm + u0);
            top[0]=img[vm+ul]; top[1]=q.x; top[2]=q.y; top[3]=q.z; top[4]=q.w; top[5]=img[vm+ur];
            q = *(const float4*)(img + v0r + u0);
            mid[0]=img[v0r+ul]; mid[1]=q.x; mid[2]=q.y; mid[3]=q.z; mid[4]=q.w; mid[5]=img[v0r+ur];
            q = *(const float4*)(img + vp + u0);
            bot[0]=img[vp+ul]; bot[1]=q.x; bot[2]=q.y; bot[3]=q.z; bot[4]=q.w; bot[5]=img[vp+ur];

            float4 s0v = *(const float4*)(sigma0 + off + p4);
            float4 xv  = *(const float4*)(x1 + off + p4);
            float4 sv  = *(const float4*)(sigma1 + off + p4);
            s0a[ch][0]=s0v.x; s0a[ch][1]=s0v.y; s0a[ch][2]=s0v.z; s0a[ch][3]=s0v.w;
            x1a[ch][0]=xv.x;  x1a[ch][1]=xv.y;  x1a[ch][2]=xv.z;  x1a[ch][3]=xv.w;
            s1a[ch][0]=sv.x;  s1a[ch][1]=sv.y;  s1a[ch][2]=sv.z;  s1a[ch][3]=sv.w;

#pragma unroll
            for (int i = 0; i < 4; i++) {
                float tl = top[i], tc_ = top[i+1], tr = top[i+2];
                float ml = mid[i],                 mr = mid[i+2];
                float bl = bot[i], bc_ = bot[i+1], br = bot[i+2];
                float dx = tr - tl + 2.0f*(mr - ml) + (br - bl);
                float dy = bl - tl + 2.0f*(bc_ - tc_) + (br - tr);
                float rinv = rsqrtf(dx*dx + dy*dy + 1e-8f);
                av[ch][i] = dx*rinv;
                gv[ch][i] = dy*rinv;
                x0a[ch][i] = mid[i+1];
            }
        }
#pragma unroll
        for (int i = 0; i < 4; i++) {
            agw[pair][i] = pack_fp8x4(av[0][i], av[1][i], gv[0][i], gv[1][i]);
            xsw[pair][i] = pack_fp8x4(x0a[0][i], x0a[1][i], s0a[0][i], s0a[1][i]);
            x1p[pair][i] = pack_fp8x2(x1a[0][i], x1a[1][i]);
            s1p[pair][i] = pack_fp8x2(s1a[0][i], s1a[1][i]);
        }
    }

    // cen stores: pair planes (quad*2, quad*2+1)
#pragma unroll
    for (int pair = 0; pair < 2; pair++) {
        size_t cpl = (size_t)(b*PAIRS + quad*2 + pair)*NN + p4;
        uint4* co = (uint4*)&g_cen4[cpl];
        co[0] = make_uint4(agw[pair][0], xsw[pair][0], agw[pair][1], xsw[pair][1]);
        co[1] = make_uint4(agw[pair][2], xsw[pair][2], agw[pair][3], xsw[pair][3]);
    }
    // gather stores: quad plane, uint2 per px {x1 quad word, s1 quad word}
    size_t gpl = (size_t)bq*NN + p4;
    uint4* go = (uint4*)&g_gathq[gpl];
    go[0] = make_uint4((unsigned)x1p[0][0] | ((unsigned)x1p[1][0] << 16),
                       (unsigned)s1p[0][0] | ((unsigned)s1p[1][0] << 16),
                       (unsigned)x1p[0][1] | ((unsigned)x1p[1][1] << 16),
                       (unsigned)s1p[0][1] | ((unsigned)s1p[1][1] << 16));
    go[1] = make_uint4((unsigned)x1p[0][2] | ((unsigned)x1p[1][2] << 16),
                       (unsigned)s1p[0][2] | ((unsigned)s1p[1][2] << 16),
                       (unsigned)x1p[0][3] | ((unsigned)x1p[1][3] << 16),
                       (unsigned)s1p[0][3] | ((unsigned)s1p[1][3] << 16));
}

// ---------------- fused per-iteration accumulation + last-block solve ----------------
__global__ __launch_bounds__(256)
void iterKernel(const float* __restrict__ invD0, const float* __restrict__ invD1,
                const float* __restrict__ Kmat, float* __restrict__ out, int last)
{
    const int b  = blockIdx.y;
    const int p2 = (blockIdx.x * 256 + threadIdx.x) * 2;

    __shared__ float sm[27][8];

    float acc[27];
#pragma unroll
    for (int k = 0; k < 27; k++) acc[k] = 0.0f;

    {
        const float fx = Kmat[b*4+0], fy = Kmat[b*4+1];
        const float cx = Kmat[b*4+2], cy = Kmat[b*4+3];
        const float ifx = 1.0f/fx, ify = 1.0f/fy;
        const float* Rb = g_R[b];
        const float* tb = g_t[b];

        int vpix = p2 / WW;
        int u0   = p2 - vpix*WW;
        float y  = ((float)vpix - cy) * ify;
        float2 d2 = *(const float2*)(invD0 + (size_t)b*NN + p2);
        float dd[2] = {d2.x, d2.y};

        float xs_[2], valid[2];
        __half2 w00h[2], w01h[2], w10h[2], w11h[2];
        int o00[2], o01[2], o10[2], o11[2];
        const float* D1 = invD1 + (size_t)b*NN;

#pragma unroll
        for (int i = 0; i < 2; i++) {
            float x = ((float)(u0 + i) - cx) * ifx;
            xs_[i] = x;
            float d = dd[i];
            float X = Rb[0]*x + Rb[1]*y + Rb[2] + tb[0]*d;
            float Y = Rb[3]*x + Rb[4]*y + Rb[5] + tb[1]*d;
            float S = Rb[6]*x + Rb[7]*y + Rb[8] + tb[2]*d;
            float invS = __fdividef(1.0f, S);
            float u = X * invS * fx + cx;
            float v = Y * invS * fy + cy;
            float invz = d * invS;

            float uc = fminf(fmaxf(u, 0.0f), (float)(WW-1));
            float vc = fminf(fmaxf(v, 0.0f), (float)(HH-1));
            float x0f = floorf(uc), y0f = floorf(vc);
            float wx = uc - x0f, wy = vc - y0f;
            int xi0 = (int)x0f, yi0 = (int)y0f;
            int xi1 = min(xi0 + 1, WW-1), yi1 = min(yi0 + 1, HH-1);
            float w00 = (1.0f-wx)*(1.0f-wy), w01 = wx*(1.0f-wy);
            float w10 = (1.0f-wx)*wy,        w11 = wx*wy;
            o00[i] = yi0*WW + xi0; o01[i] = yi0*WW + xi1;
            o10[i] = yi1*WW + xi0; o11[i] = yi1*WW + xi1;
            w00h[i] = __float2half2_rn(w00); w01h[i] = __float2half2_rn(w01);
            w10h[i] = __float2half2_rn(w10); w11h[i] = __float2half2_rn(w11);

            float dz = D1[o00[i]]*w00 + D1[o01[i]]*w01 + D1[o10[i]]*w10 + D1[o11[i]]*w11;
            bool inlier = invz > dz - 0.1f;
            bool inview = (u > 0.0f) && (u < (float)WW) && (v > 0.0f) && (v < (float)HH);
            valid[i] = (inlier && inview) ? 1.0f : 0.0f;
        }

        // half2 S-accumulators (lanes = channels of a pair), per pixel
        __half2 Saah[2], Sabh[2], Sbbh[2], Sarh[2], Sbrh[2];
#pragma unroll
        for (int i = 0; i < 2; i++) {
            Saah[i] = __float2half2_rn(0.0f); Sabh[i] = Saah[i]; Sbbh[i] = Saah[i];
            Sarh[i] = Saah[i]; Sbrh[i] = Saah[i];
        }

#pragma unroll
        for (int quad = 0; quad < QUADS; quad++) {
            size_t cplA = (size_t)(b*PAIRS + quad*2)*NN;       // pair 2q
            // cen: streaming loads (zero reuse) — keep out of L1 (__ldcs)
            uint4 cvA = __ldcs((const uint4*)&g_cen4[cplA + p2]);        // pair 2q,   px0+px1
            uint4 cvB = __ldcs((const uint4*)&g_cen4[cplA + NN + p2]);   // pair 2q+1, px0+px1
            const uint2* G = g_gathq + (size_t)(b*QUADS + quad)*NN;
            unsigned agA[2] = {cvA.x, cvA.z}, xsA[2] = {cvA.y, cvA.w};
            unsigned agB[2] = {cvB.x, cvB.z}, xsB[2] = {cvB.y, cvB.w};
#pragma unroll
            for (int i = 0; i < 2; i++) {
                uint2 q00 = __ldg(G + o00[i]);
                uint2 q01 = __ldg(G + o01[i]);
                uint2 q10 = __ldg(G + o10[i]);
                uint2 q11 = __ldg(G + o11[i]);
                // bilinear x1, pair0 (lanes=channels c0,c1) and pair1 (c2,c3)
                __half2 fr0 = __hmul2(fp8x2_to_h2((unsigned short)(q00.x & 0xFFFFu)), w00h[i]);
                fr0 = __hfma2(fp8x2_to_h2((unsigned short)(q01.x & 0xFFFFu)), w01h[i], fr0);
                fr0 = __hfma2(fp8x2_to_h2((unsigned short)(q10.x & 0xFFFFu)), w10h[i], fr0);
                fr0 = __hfma2(fp8x2_to_h2((unsigned short)(q11.x & 0xFFFFu)), w11h[i], fr0);
                __half2 fr1 = __hmul2(fp8x2_to_h2((unsigned short)(q00.x >> 16)), w00h[i]);
                fr1 = __hfma2(fp8x2_to_h2((unsigned short)(q01.x >> 16)), w01h[i], fr1);
                fr1 = __hfma2(fp8x2_to_h2((unsigned short)(q10.x >> 16)), w10h[i], fr1);
                fr1 = __hfma2(fp8x2_to_h2((unsigned short)(q11.x >> 16)), w11h[i], fr1);
                // bilinear sigma1
                __half2 sr0 = __hmul2(fp8x2_to_h2((unsigned short)(q00.y & 0xFFFFu)), w00h[i]);
                sr0 = __hfma2(fp8x2_to_h2((unsigned short)(q01.y & 0xFFFFu)), w01h[i], sr0);
                sr0 = __hfma2(fp8x2_to_h2((unsigned short)(q10.y & 0xFFFFu)), w10h[i], sr0);
                sr0 = __hfma2(fp8x2_to_h2((unsigned short)(q11.y & 0xFFFFu)), w11h[i], sr0);
                __half2 sr1 = __hmul2(fp8x2_to_h2((unsigned short)(q00.y >> 16)), w00h[i]);
                sr1 = __hfma2(fp8x2_to_h2((unsigned short)(q01.y >> 16)), w01h[i], sr1);
                sr1 = __hfma2(fp8x2_to_h2((unsigned short)(q10.y >> 16)), w10h[i], sr1);
                sr1 = __hfma2(fp8x2_to_h2((unsigned short)(q11.y >> 16)), w11h[i], sr1);

#pragma unroll
                for (int pr = 0; pr < 2; pr++) {
                    unsigned agu = (pr == 0) ? agA[i] : agB[i];
                    unsigned xsu = (pr == 0) ? xsA[i] : xsB[i];
                    __half2 frh = (pr == 0) ? fr0 : fr1;
                    __half2 srh = (pr == 0) ? sr0 : sr1;
                    __half2 ha  = fp8x2_to_h2((unsigned short)(agu & 0xFFFFu));
                    __half2 hg  = fp8x2_to_h2((unsigned short)(agu >> 16));
                    __half2 hx0 = fp8x2_to_h2((unsigned short)(xsu & 0xFFFFu));
                    __half2 hs0 = fp8x2_to_h2((unsigned short)(xsu >> 16));

                    __half2 s2h  = __hfma2(srh, srh, __hmul2(hs0, hs0));
                    __half2 wgth = h2rcp(s2h);
                    __half2 resh = __hsub2(frh, hx0);
                    __half2 awh  = __hmul2(ha, wgth);
                    __half2 gwh  = __hmul2(hg, wgth);
                    Saah[i] = __hfma2(awh, ha,   Saah[i]);
                    Sabh[i] = __hfma2(awh, hg,   Sabh[i]);
                    Sbbh[i] = __hfma2(gwh, hg,   Sbbh[i]);
                    Sarh[i] = __hfma2(awh, resh, Sarh[i]);
                    Sbrh[i] = __hfma2(gwh, resh, Sbrh[i]);
                }
            }
        }

        // per-pixel: horizontal-sum channels, mask, factorized 27-expansion
#pragma unroll
        for (int i = 0; i < 2; i++) {
            float2 t;
            t = __half22float2(Saah[i]); float Saa = (t.x + t.y) * valid[i];
            t = __half22float2(Sabh[i]); float Sab = (t.x + t.y) * valid[i];
            t = __half22float2(Sbbh[i]); float Sbb = (t.x + t.y) * valid[i];
            t = __half22float2(Sarh[i]); float Sar = (t.x + t.y) * valid[i];
            t = __half22float2(Sbrh[i]); float Sbr = (t.x + t.y) * valid[i];

            float x = xs_[i], d = dd[i];
            float xy = x*y;
            float Jx[6], Jy[6];
            Jx[0] = -xy*fx;          Jx[1] = (1.0f + x*x)*fx; Jx[2] = -y*fx;
            Jx[3] = d*fx;            Jx[4] = 0.0f;            Jx[5] = -d*x*fx;
            Jy[0] = -(1.0f+y*y)*fy;  Jy[1] = xy*fy;           Jy[2] = x*fy;
            Jy[3] = 0.0f;            Jy[4] = d*fy;            Jy[5] = -d*y*fy;

            float uu[6], vv[6];
#pragma unroll
            for (int k = 0; k < 6; k++) {
                uu[k] = Saa*Jx[k] + Sab*Jy[k];
                vv[k] = Sab*Jx[k] + Sbb*Jy[k];
            }
            int idx = 0;
#pragma unroll
            for (int k = 0; k < 6; k++) {
#pragma unroll
                for (int l = k; l < 6; l++) {
                    acc[idx++] += uu[k]*Jx[l] + vv[k]*Jy[l];
                }
            }
#pragma unroll
            for (int k = 0; k < 6; k++) acc[21+k] += Sar*Jx[k] + Sbr*Jy[k];
        }
    }

    // ---- block reduction of 27 values, then per-block atomicAdd ----
#pragma unroll
    for (int k = 0; k < 27; k++) {
#pragma unroll
        for (int off = 16; off > 0; off >>= 1)
            acc[k] += __shfl_down_sync(0xFFFFFFFFu, acc[k], off);
    }
    int lane = threadIdx.x & 31;
    int warp = threadIdx.x >> 5;
    if (lane == 0) {
#pragma unroll
        for (int k = 0; k < 27; k++) sm[k][warp] = acc[k];
    }
    __syncthreads();
    if (threadIdx.x < 27) {
        float s = 0.0f;
#pragma unroll
        for (int w = 0; w < 8; w++) s += sm[threadIdx.x][w];
        // RETURNING atomic: consuming 'old' forces the RMW to complete at L2
        // (device point of coherence) before this thread reaches the barrier.
        // Avoids __threadfence() (CCTL.IVALL = full L1D flush).
        float old = atomicAdd(&g_acc[blockIdx.y][threadIdx.x], s);
        if (__float_as_uint(old) == 0x7f800123u) sm[0][0] = old;  // consume (never taken)
    }
    __syncthreads();

    // ---- last-block-does-solve ----
    __shared__ bool sLast;
    if (threadIdx.x == 0) {
        unsigned int done = atomicAdd(&g_count, 1u);
        sLast = (done == ITER_BLOCKS - 1);
    }
    __syncthreads();
    if (!sLast) return;
    if (threadIdx.x == 0) g_count = 0;

    if (threadIdx.x < BB) {
        int bb = threadIdx.x;
        float M[6][7];
        {
            float Jt[6][6];
            int idx = 0;
#pragma unroll
            for (int k = 0; k < 6; k++)
#pragma unroll
                for (int l = k; l < 6; l++) {
                    float vvv = __ldcg(&g_acc[bb][idx]);  // L2 read, bypass L1
                    idx++;
                    Jt[k][l] = vvv; Jt[l][k] = vvv;
                }
            float tr = 0.0f;
#pragma unroll
            for (int k = 0; k < 6; k++) tr += Jt[k][k];
            float lam = tr * 1e-6f;
#pragma unroll
            for (int i = 0; i < 6; i++) {
#pragma unroll
                for (int j = 0; j < 6; j++) M[i][j] = Jt[i][j] + (i == j ? lam : 0.0f);
                M[i][6] = __ldcg(&g_acc[bb][21+i]);
            }
        }
        for (int k = 0; k < 6; k++) {
            int piv = k; float mx = fabsf(M[k][k]);
            for (int i = k+1; i < 6; i++) {
                float a = fabsf(M[i][k]);
                if (a > mx) { mx = a; piv = i; }
            }
            if (piv != k)
                for (int j = k; j < 7; j++) { float tmp = M[k][j]; M[k][j] = M[piv][j]; M[piv][j] = tmp; }
            float inv = 1.0f / M[k][k];
            for (int i = k+1; i < 6; i++) {
                float f = M[i][k] * inv;
                for (int j = k; j < 7; j++) M[i][j] -= f * M[k][j];
            }
        }
        float xi[6];
        for (int i = 5; i >= 0; i--) {
            float s = M[i][6];
            for (int j = i+1; j < 6; j++) s -= M[i][j] * xi[j];
            xi[i] = s / M[i][i];
        }

        float dR[9];
        rodrigues(-xi[0], -xi[1], -xi[2], dR);
        float dt[3];
        dt[0] = -(dR[0]*xi[3] + dR[1]*xi[4] + dR[2]*xi[5]);
        dt[1] = -(dR[3]*xi[3] + dR[4]*xi[4] + dR[5]*xi[5]);
        dt[2] = -(dR[6]*xi[3] + dR[7]*xi[4] + dR[8]*xi[5]);

        float Rb[9], tb[3];
#pragma unroll
        for (int i = 0; i < 9; i++) Rb[i] = g_R[bb][i];
#pragma unroll
        for (int i = 0; i < 3; i++) tb[i] = g_t[bb][i];

        float nt[3], nR[9];
#pragma unroll
        for (int i = 0; i < 3; i++)
            nt[i] = Rb[i*3+0]*dt[0] + Rb[i*3+1]*dt[1] + Rb[i*3+2]*dt[2] + tb[i];
#pragma unroll
        for (int i = 0; i < 3; i++)
#pragma unroll
            for (int j = 0; j < 3; j++)
                nR[i*3+j] = Rb[i*3+0]*dR[0*3+j] + Rb[i*3+1]*dR[1*3+j] + Rb[i*3+2]*dR[2*3+j];

#pragma unroll
        for (int i = 0; i < 9; i++) g_R[bb][i] = nR[i];
#pragma unroll
        for (int i = 0; i < 3; i++) g_t[bb][i] = nt[i];
#pragma unroll
        for (int k = 0; k < 27; k++) g_acc[bb][k] = 0.0f;

        if (last) {
#pragma unroll
            for (int i = 0; i < 9; i++) out[bb*12 + i] = nR[i];
#pragma unroll
            for (int i = 0; i < 3; i++) out[bb*12 + 9 + i] = nt[i];
        }
    }
}

// ---------------- launch ----------------
extern "C" void kernel_launch(void* const* d_in, const int* in_sizes, int n_in,
                              void* d_out, int out_size) {
    const float* twist0 = (const float*)d_in[0];
    const float* x0     = (const float*)d_in[1];
    const float* x1     = (const float*)d_in[2];
    const float* invD0  = (const float*)d_in[3];
    const float* invD1  = (const float*)d_in[4];
    const float* sigma0 = (const float*)d_in[5];
    const float* sigma1 = (const float*)d_in[6];
    const float* Kmat   = (const float*)d_in[7];
    float* out = (float*)d_out;

    packKernel<<<BB*QUADS*(NN/4)/256, 256>>>(twist0, x0, sigma0, x1, sigma1);
    for (int it = 0; it < 3; ++it) {
        dim3 grid(NN/2/256, BB);
        iterKernel<<<grid, 256>>>(invD0, invD1, Kmat, out, it == 2);
    }
}

// round 15
// speedup vs baseline: 1.0627x; 1.0627x over previous
#include <cuda_runtime.h>
#include <cuda_fp16.h>
#include <cuda_fp8.h>
#include <math.h>

#define BB 8
#define CC 16
#define PAIRS (CC/2)
#define HH 240
#define WW 320
#define NN (HH*WW)
#define ITER_BLOCKS (NN/2/256*BB)   // 150*8 = 1200

// ---------------- device-global state (no allocations allowed) ----------------
__device__ float g_R[BB][9];
__device__ float g_t[BB][3];
__device__ float g_acc[BB][27];            // 21 upper-tri JtWJ + 6 Rhs
__device__ unsigned int g_count;           // last-block counter (zero at load; reset after use)
// channel-lane layouts over (b,pair,p); lanes of each 16-bit half are the 2 channels:
//   g_cen4 : uint2 { fp8x4{a_c0,a_c1,g_c0,g_c1}, fp8x4{x0_c0,x0_c1,s0_c0,s0_c1} }
//   g_gath4: u32     fp8x4{x1_c0,x1_c1,s1_c0,s1_c1}
__device__ uint2    g_cen4[BB*PAIRS*NN];
__device__ unsigned g_gath4[BB*PAIRS*NN];

__device__ __forceinline__ unsigned pack_fp8x4(float a, float b, float c, float d) {
    __nv_fp8x2_storage_t lo = __nv_cvt_float2_to_fp8x2(make_float2(a, b), __NV_SATFINITE, __NV_E4M3);
    __nv_fp8x2_storage_t hi = __nv_cvt_float2_to_fp8x2(make_float2(c, d), __NV_SATFINITE, __NV_E4M3);
    return (unsigned)lo | ((unsigned)hi << 16);
}
__device__ __forceinline__ __half2 fp8x2_to_h2(unsigned short v) {
    __half2_raw r = __nv_cvt_fp8x2_to_halfraw2((__nv_fp8x2_storage_t)v, __NV_E4M3);
    return *(__half2*)&r;
}

__device__ __forceinline__ void rodrigues(float wx, float wy, float wz, float* R) {
    float th = sqrtf(wx*wx + wy*wy + wz*wz) + 1e-12f;
    float inv = 1.0f / th;
    float ax = wx*inv, ay = wy*inv, az = wz*inv;
    float s = sinf(th), c = cosf(th), mc = 1.0f - c;
    R[0] = c + mc*ax*ax;     R[1] = mc*ax*ay - s*az;  R[2] = mc*ax*az + s*ay;
    R[3] = mc*ax*ay + s*az;  R[4] = c + mc*ay*ay;     R[5] = mc*ay*az - s*ax;
    R[6] = mc*ax*az - s*ay;  R[7] = mc*ay*az + s*ax;  R[8] = c + mc*az*az;
}

// ---------------- pack: sobel + fp8 channel-lane layouts; init fused ----------------
__global__ __launch_bounds__(256)
void packKernel(const float* __restrict__ twist0, const float* __restrict__ x0,
                const float* __restrict__ sigma0, const float* __restrict__ x1,
                const float* __restrict__ sigma1) {
    if (blockIdx.x == 0 && threadIdx.x < BB) {      // fused init
        int b = threadIdx.x;
        rodrigues(twist0[b*6+0], twist0[b*6+1], twist0[b*6+2], g_R[b]);
        g_t[b][0] = twist0[b*6+3];
        g_t[b][1] = twist0[b*6+4];
        g_t[b][2] = twist0[b*6+5];
#pragma unroll
        for (int k = 0; k < 27; k++) g_acc[b][k] = 0.0f;
    }

    int t = blockIdx.x * 256 + threadIdx.x;         // one thread = 4 pixels, one channel-pair
    int nPix4 = NN / 4;
    int p4  = (t % nPix4) * 4;
    int bp  = t / nPix4;                             // 0..BB*PAIRS-1
    int b    = bp >> 3;
    int pair = bp & 7;
    int v  = p4 / WW;
    int u0 = p4 - v*WW;                              // %4==0, row-contained

    int vm = max(v-1, 0)*WW, v0r = v*WW, vp = min(v+1, HH-1)*WW;
    int ul = max(u0-1, 0);
    int ur = min(u0+4, WW-1);

    float av[2][4], gv[2][4], x0a[2][4], s0a[2][4], x1a[2][4], s1a[2][4];
#pragma unroll
    for (int ch = 0; ch < 2; ch++) {
        int c = pair*2 + ch;
        size_t off = (size_t)(b*CC + c)*NN;
        const float* img = x0 + off;

        float top[6], mid[6], bot[6];
        float4 q;
        q = *(const float4*)(img + vm + u0);
        top[0]=img[vm+ul]; top[1]=q.x; top[2]=q.y; top[3]=q.z; top[4]=q.w; top[5]=img[vm+ur];
        q = *(const float4*)(img + v0r + u0);
        mid[0]=img[v0r+ul]; mid[1]=q.x; mid[2]=q.y; mid[3]=q.z; mid[4]=q.w; mid[5]=img[v0r+ur];
        q = *(const float4*)(img + vp + u0);
        bot[0]=img[vp+ul]; bot[1]=q.x; bot[2]=q.y; bot[3]=q.z; bot[4]=q.w; bot[5]=img[vp+ur];

        float4 s0v = *(const float4*)(sigma0 + off + p4);
        float4 xv  = *(const float4*)(x1 + off + p4);
        float4 sv  = *(const float4*)(sigma1 + off + p4);
        s0a[ch][0]=s0v.x; s0a[ch][1]=s0v.y; s0a[ch][2]=s0v.z; s0a[ch][3]=s0v.w;
        x1a[ch][0]=xv.x;  x1a[ch][1]=xv.y;  x1a[ch][2]=xv.z;  x1a[ch][3]=xv.w;
        s1a[ch][0]=sv.x;  s1a[ch][1]=sv.y;  s1a[ch][2]=sv.z;  s1a[ch][3]=sv.w;

#pragma unroll
        for (int i = 0; i < 4; i++) {
            float tl = top[i], tc_ = top[i+1], tr = top[i+2];
            float ml = mid[i],                 mr = mid[i+2];
            float bl = bot[i], bc_ = bot[i+1], br = bot[i+2];
            float dx = tr - tl + 2.0f*(mr - ml) + (br - bl);
            float dy = bl - tl + 2.0f*(bc_ - tc_) + (br - tr);
            float rinv = rsqrtf(dx*dx + dy*dy + 1e-8f);
            av[ch][i] = dx*rinv;
            gv[ch][i] = dy*rinv;
            x0a[ch][i] = mid[i+1];
        }
    }

    size_t plane = (size_t)bp*NN + p4;
    uint4* co = (uint4*)&g_cen4[plane];
#pragma unroll
    for (int h = 0; h < 2; h++) {
        int i0 = h*2, i1 = h*2 + 1;
        co[h] = make_uint4(
            pack_fp8x4(av[0][i0], av[1][i0], gv[0][i0], gv[1][i0]),
            pack_fp8x4(x0a[0][i0], x0a[1][i0], s0a[0][i0], s0a[1][i0]),
            pack_fp8x4(av[0][i1], av[1][i1], gv[0][i1], gv[1][i1]),
            pack_fp8x4(x0a[0][i1], x0a[1][i1], s0a[0][i1], s0a[1][i1]));
    }
    *(uint4*)&g_gath4[plane] = make_uint4(
        pack_fp8x4(x1a[0][0], x1a[1][0], s1a[0][0], s1a[1][0]),
        pack_fp8x4(x1a[0][1], x1a[1][1], s1a[0][1], s1a[1][1]),
        pack_fp8x4(x1a[0][2], x1a[1][2], s1a[0][2], s1a[1][2]),
        pack_fp8x4(x1a[0][3], x1a[1][3], s1a[0][3], s1a[1][3]));
}

// ---------------- fused per-iteration accumulation + last-block solve ----------------
__global__ __launch_bounds__(256)
void iterKernel(const float* __restrict__ invD0, const float* __restrict__ invD1,
                const float* __restrict__ Kmat, float* __restrict__ out, int last)
{
    const int b  = blockIdx.y;
    const int p2 = (blockIdx.x * 256 + threadIdx.x) * 2;

    __shared__ float sm[27][8];

    float acc[27];
#pragma unroll
    for (int k = 0; k < 27; k++) acc[k] = 0.0f;

    {
        const float fx = Kmat[b*4+0], fy = Kmat[b*4+1];
        const float cx = Kmat[b*4+2], cy = Kmat[b*4+3];
        const float ifx = 1.0f/fx, ify = 1.0f/fy;
        const float* Rb = g_R[b];
        const float* tb = g_t[b];

        int vpix = p2 / WW;
        int u0   = p2 - vpix*WW;
        float y  = ((float)vpix - cy) * ify;
        float2 d2 = *(const float2*)(invD0 + (size_t)b*NN + p2);
        float dd[2] = {d2.x, d2.y};

        float xs_[2], valid[2];
        __half2 w00h[2], w01h[2], w10h[2], w11h[2];
        int o00[2], o01[2], o10[2], o11[2];
        const float* D1 = invD1 + (size_t)b*NN;

#pragma unroll
        for (int i = 0; i < 2; i++) {
            float x = ((float)(u0 + i) - cx) * ifx;
            xs_[i] = x;
            float d = dd[i];
            float X = Rb[0]*x + Rb[1]*y + Rb[2] + tb[0]*d;
            float Y = Rb[3]*x + Rb[4]*y + Rb[5] + tb[1]*d;
            float S = Rb[6]*x + Rb[7]*y + Rb[8] + tb[2]*d;
            float invS = __fdividef(1.0f, S);
            float u = X * invS * fx + cx;
            float v = Y * invS * fy + cy;
            float invz = d * invS;

            float uc = fminf(fmaxf(u, 0.0f), (float)(WW-1));
            float vc = fminf(fmaxf(v, 0.0f), (float)(HH-1));
            float x0f = floorf(uc), y0f = floorf(vc);
            float wx = uc - x0f, wy = vc - y0f;
            int xi0 = (int)x0f, yi0 = (int)y0f;
            int xi1 = min(xi0 + 1, WW-1), yi1 = min(yi0 + 1, HH-1);
            float w00 = (1.0f-wx)*(1.0f-wy), w01 = wx*(1.0f-wy);
            float w10 = (1.0f-wx)*wy,        w11 = wx*wy;
            o00[i] = yi0*WW + xi0; o01[i] = yi0*WW + xi1;
            o10[i] = yi1*WW + xi0; o11[i] = yi1*WW + xi1;
            w00h[i] = __float2half2_rn(w00); w01h[i] = __float2half2_rn(w01);
            w10h[i] = __float2half2_rn(w10); w11h[i] = __float2half2_rn(w11);

            float dz = D1[o00[i]]*w00 + D1[o01[i]]*w01 + D1[o10[i]]*w10 + D1[o11[i]]*w11;
            bool inlier = invz > dz - 0.1f;
            bool inview = (u > 0.0f) && (u < (float)WW) && (v > 0.0f) && (v < (float)HH);
            valid[i] = (inlier && inview) ? 1.0f : 0.0f;
        }

        // half2 S-accumulators (lanes = channels of a pair), per pixel
        __half2 Saah[2], Sabh[2], Sbbh[2], Sarh[2], Sbrh[2];
#pragma unroll
        for (int i = 0; i < 2; i++) {
            Saah[i] = __float2half2_rn(0.0f); Sabh[i] = Saah[i]; Sbbh[i] = Saah[i];
            Sarh[i] = Saah[i]; Sbrh[i] = Saah[i];
        }

#pragma unroll
        for (int pair = 0; pair < PAIRS; pair++) {
            size_t plane = (size_t)(b*PAIRS + pair)*NN;
            // cen: read exactly once per iteration (zero reuse) -> evict-first,
            // keep L1 capacity for the heavily-reused gather planes.
            uint4 cvq = __ldcs((const uint4*)&g_cen4[plane + p2]);  // 2 px × uint2
            const unsigned* G = g_gath4 + plane;
            unsigned cenA[2] = {cvq.x, cvq.z};   // {a,g} words
            unsigned cenB[2] = {cvq.y, cvq.w};   // {x0,s0} words
#pragma unroll
            for (int i = 0; i < 2; i++) {
                unsigned q00 = __ldg(G + o00[i]);
                unsigned q01 = __ldg(G + o01[i]);
                unsigned q10 = __ldg(G + o10[i]);
                unsigned q11 = __ldg(G + o11[i]);
                // bilinear x1 (lanes=channels)
                __half2 frh = __hmul2(fp8x2_to_h2((unsigned short)(q00 & 0xFFFFu)), w00h[i]);
                frh = __hfma2(fp8x2_to_h2((unsigned short)(q01 & 0xFFFFu)), w01h[i], frh);
                frh = __hfma2(fp8x2_to_h2((unsigned short)(q10 & 0xFFFFu)), w10h[i], frh);
                frh = __hfma2(fp8x2_to_h2((unsigned short)(q11 & 0xFFFFu)), w11h[i], frh);
                // bilinear sigma1
                __half2 srh = __hmul2(fp8x2_to_h2((unsigned short)(q00 >> 16)), w00h[i]);
                srh = __hfma2(fp8x2_to_h2((unsigned short)(q01 >> 16)), w01h[i], srh);
                srh = __hfma2(fp8x2_to_h2((unsigned short)(q10 >> 16)), w10h[i], srh);
                srh = __hfma2(fp8x2_to_h2((unsigned short)(q11 >> 16)), w11h[i], srh);

                __half2 ha  = fp8x2_to_h2((unsigned short)(cenA[i] & 0xFFFFu));
                __half2 hg  = fp8x2_to_h2((unsigned short)(cenA[i] >> 16));
                __half2 hx0 = fp8x2_to_h2((unsigned short)(cenB[i] & 0xFFFFu));
                __half2 hs0 = fp8x2_to_h2((unsigned short)(cenB[i] >> 16));

                __half2 s2h  = __hfma2(srh, srh, __hmul2(hs0, hs0));
                __half2 wgth = h2rcp(s2h);
                __half2 resh = __hsub2(frh, hx0);
                __half2 awh  = __hmul2(ha, wgth);
                __half2 gwh  = __hmul2(hg, wgth);
                Saah[i] = __hfma2(awh, ha,   Saah[i]);
                Sabh[i] = __hfma2(awh, hg,   Sabh[i]);
                Sbbh[i] = __hfma2(gwh, hg,   Sbbh[i]);
                Sarh[i] = __hfma2(awh, resh, Sarh[i]);
                Sbrh[i] = __hfma2(gwh, resh, Sbrh[i]);
            }
        }

        // per-pixel: horizontal-sum channels, mask, factorized 27-expansion
#pragma unroll
        for (int i = 0; i < 2; i++) {
            float2 t;
            t = __half22float2(Saah[i]); float Saa = (t.x + t.y) * valid[i];
            t = __half22float2(Sabh[i]); float Sab = (t.x + t.y) * valid[i];
            t = __half22float2(Sbbh[i]); float Sbb = (t.x + t.y) * valid[i];
            t = __half22float2(Sarh[i]); float Sar = (t.x + t.y) * valid[i];
            t = __half22float2(Sbrh[i]); float Sbr = (t.x + t.y) * valid[i];

            float x = xs_[i], d = dd[i];
            float xy = x*y;
            float Jx[6], Jy[6];
            Jx[0] = -xy*fx;          Jx[1] = (1.0f + x*x)*fx; Jx[2] = -y*fx;
            Jx[3] = d*fx;            Jx[4] = 0.0f;            Jx[5] = -d*x*fx;
            Jy[0] = -(1.0f+y*y)*fy;  Jy[1] = xy*fy;           Jy[2] = x*fy;
            Jy[3] = 0.0f;            Jy[4] = d*fy;            Jy[5] = -d*y*fy;

            float uu[6], vv[6];
#pragma unroll
            for (int k = 0; k < 6; k++) {
                uu[k] = Saa*Jx[k] + Sab*Jy[k];
                vv[k] = Sab*Jx[k] + Sbb*Jy[k];
            }
            int idx = 0;
#pragma unroll
            for (int k = 0; k < 6; k++) {
#pragma unroll
                for (int l = k; l < 6; l++) {
                    acc[idx++] += uu[k]*Jx[l] + vv[k]*Jy[l];
                }
            }
#pragma unroll
            for (int k = 0; k < 6; k++) acc[21+k] += Sar*Jx[k] + Sbr*Jy[k];
        }
    }

    // ---- block reduction of 27 values, then per-block atomicAdd ----
#pragma unroll
    for (int k = 0; k < 27; k++) {
#pragma unroll
        for (int off = 16; off > 0; off >>= 1)
            acc[k] += __shfl_down_sync(0xFFFFFFFFu, acc[k], off);
    }
    int lane = threadIdx.x & 31;
    int warp = threadIdx.x >> 5;
    if (lane == 0) {
#pragma unroll
        for (int k = 0; k < 27; k++) sm[k][warp] = acc[k];
    }
    __syncthreads();
    if (threadIdx.x < 27) {
        float s = 0.0f;
#pragma unroll
        for (int w = 0; w < 8; w++) s += sm[threadIdx.x][w];
        // RETURNING atomic: consuming 'old' forces the RMW to complete at L2
        // (device point of coherence) before this thread reaches the barrier.
        // Avoids __threadfence() (CCTL.IVALL = full L1D flush).
        float old = atomicAdd(&g_acc[blockIdx.y][threadIdx.x], s);
        if (__float_as_uint(old) == 0x7f800123u) sm[0][0] = old;  // consume (never taken)
    }
    __syncthreads();

    // ---- last-block-does-solve ----
    __shared__ bool sLast;
    if (threadIdx.x == 0) {
        unsigned int done = atomicAdd(&g_count, 1u);
        sLast = (done == ITER_BLOCKS - 1);
    }
    __syncthreads();
    if (!sLast) return;
    if (threadIdx.x == 0) g_count = 0;

    if (threadIdx.x < BB) {
        int bb = threadIdx.x;
        float M[6][7];
        {
            float Jt[6][6];
            int idx = 0;
#pragma unroll
            for (int k = 0; k < 6; k++)
#pragma unroll
                for (int l = k; l < 6; l++) {
                    float vvv = __ldcg(&g_acc[bb][idx]);  // L2 read, bypass L1
                    idx++;
                    Jt[k][l] = vvv; Jt[l][k] = vvv;
                }
            float tr = 0.0f;
#pragma unroll
            for (int k = 0; k < 6; k++) tr += Jt[k][k];
            float lam = tr * 1e-6f;
#pragma unroll
            for (int i = 0; i < 6; i++) {
#pragma unroll
                for (int j = 0; j < 6; j++) M[i][j] = Jt[i][j] + (i == j ? lam : 0.0f);
                M[i][6] = __ldcg(&g_acc[bb][21+i]);
            }
        }
        for (int k = 0; k < 6; k++) {
            int piv = k; float mx = fabsf(M[k][k]);
            for (int i = k+1; i < 6; i++) {
                float a = fabsf(M[i][k]);
                if (a > mx) { mx = a; piv = i; }
            }
            if (piv != k)
                for (int j = k; j < 7; j++) { float tmp = M[k][j]; M[k][j] = M[piv][j]; M[piv][j] = tmp; }
            float inv = 1.0f / M[k][k];
            for (int i = k+1; i < 6; i++) {
                float f = M[i][k] * inv;
                for (int j = k; j < 7; j++) M[i][j] -= f * M[k][j];
            }
        }
        float xi[6];
        for (int i = 5; i >= 0; i--) {
            float s = M[i][6];
            for (int j = i+1; j < 6; j++) s -= M[i][j] * xi[j];
            xi[i] = s / M[i][i];
        }

        float dR[9];
        rodrigues(-xi[0], -xi[1], -xi[2], dR);
        float dt[3];
        dt[0] = -(dR[0]*xi[3] + dR[1]*xi[4] + dR[2]*xi[5]);
        dt[1] = -(dR[3]*xi[3] + dR[4]*xi[4] + dR[5]*xi[5]);
        dt[2] = -(dR[6]*xi[3] + dR[7]*xi[4] + dR[8]*xi[5]);

        float Rb[9], tb[3];
#pragma unroll
        for (int i = 0; i < 9; i++) Rb[i] = g_R[bb][i];
#pragma unroll
        for (int i = 0; i < 3; i++) tb[i] = g_t[bb][i];

        float nt[3], nR[9];
#pragma unroll
        for (int i = 0; i < 3; i++)
            nt[i] = Rb[i*3+0]*dt[0] + Rb[i*3+1]*dt[1] + Rb[i*3+2]*dt[2] + tb[i];
#pragma unroll
        for (int i = 0; i < 3; i++)
#pragma unroll
            for (int j = 0; j < 3; j++)
                nR[i*3+j] = Rb[i*3+0]*dR[0*3+j] + Rb[i*3+1]*dR[1*3+j] + Rb[i*3+2]*dR[2*3+j];

#pragma unroll
        for (int i = 0; i < 9; i++) g_R[bb][i] = nR[i];
#pragma unroll
        for (int i = 0; i < 3; i++) g_t[bb][i] = nt[i];
#pragma unroll
        for (int k = 0; k < 27; k++) g_acc[bb][k] = 0.0f;

        if (last) {
#pragma unroll
            for (int i = 0; i < 9; i++) out[bb*12 + i] = nR[i];
#pragma unroll
            for (int i = 0; i < 3; i++) out[bb*12 + 9 + i] = nt[i];
        }
    }
}

// ---------------- launch ----------------
extern "C" void kernel_launch(void* const* d_in, const int* in_sizes, int n_in,
                              void* d_out, int out_size) {
    const float* twist0 = (const float*)d_in[0];
    const float* x0     = (const float*)d_in[1];
    const float* x1     = (const float*)d_in[2];
    const float* invD0  = (const float*)d_in[3];
    const float* invD1  = (const float*)d_in[4];
    const float* sigma0 = (const float*)d_in[5];
    const float* sigma1 = (const float*)d_in[6];
    const float* Kmat   = (const float*)d_in[7];
    float* out = (float*)d_out;

    packKernel<<<BB*PAIRS*(NN/4)/256, 256>>>(twist0, x0, sigma0, x1, sigma1);
    for (int it = 0; it < 3; ++it) {
        dim3 grid(NN/2/256, BB);
        iterKernel<<<grid, 256>>>(invD0, invD1, Kmat, out, it == 2);
    }
}

// round 16
// speedup vs baseline: 1.1250x; 1.0586x over previous
#include <cuda_runtime.h>
#include <cuda_fp16.h>
#include <cuda_fp8.h>
#include <math.h>

#define BB 8
#define CC 16
#define PAIRS (CC/2)
#define HH 240
#define WW 320
#define NN (HH*WW)
#define ITER_BLOCKS (NN/2/256*BB)   // 150*8 = 1200

// ---------------- device-global state (no allocations allowed) ----------------
__device__ float g_R[BB][9];
__device__ float g_t[BB][3];
__device__ float g_acc[BB][27];            // 21 upper-tri JtWJ + 6 Rhs
__device__ unsigned int g_count;           // last-block counter (zero at load; reset after use)
// channel-lane layouts over (b,pair,p); lanes of each 16-bit half are the 2 channels:
//   g_cen4 : uint2 { fp8x4{a_c0,a_c1,g_c0,g_c1}, fp8x4{x0_c0,x0_c1,s0_c0,s0_c1} }
//   g_gath4: u32     fp8x4{x1_c0,x1_c1,s1_c0,s1_c1}
__device__ uint2    g_cen4[BB*PAIRS*NN];
__device__ unsigned g_gath4[BB*PAIRS*NN];

__device__ __forceinline__ unsigned pack_fp8x4(float a, float b, float c, float d) {
    __nv_fp8x2_storage_t lo = __nv_cvt_float2_to_fp8x2(make_float2(a, b), __NV_SATFINITE, __NV_E4M3);
    __nv_fp8x2_storage_t hi = __nv_cvt_float2_to_fp8x2(make_float2(c, d), __NV_SATFINITE, __NV_E4M3);
    return (unsigned)lo | ((unsigned)hi << 16);
}
__device__ __forceinline__ __half2 fp8x2_to_h2(unsigned short v) {
    __half2_raw r = __nv_cvt_fp8x2_to_halfraw2((__nv_fp8x2_storage_t)v, __NV_E4M3);
    return *(__half2*)&r;
}

__device__ __forceinline__ void rodrigues(float wx, float wy, float wz, float* R) {
    float th = sqrtf(wx*wx + wy*wy + wz*wz) + 1e-12f;
    float inv = 1.0f / th;
    float ax = wx*inv, ay = wy*inv, az = wz*inv;
    float s = sinf(th), c = cosf(th), mc = 1.0f - c;
    R[0] = c + mc*ax*ax;     R[1] = mc*ax*ay - s*az;  R[2] = mc*ax*az + s*ay;
    R[3] = mc*ax*ay + s*az;  R[4] = c + mc*ay*ay;     R[5] = mc*ay*az - s*ax;
    R[6] = mc*ax*az - s*ay;  R[7] = mc*ay*az + s*ax;  R[8] = c + mc*az*az;
}

// ---------------- pack: sobel + fp8 channel-lane layouts; init fused ----------------
__global__ __launch_bounds__(256)
void packKernel(const float* __restrict__ twist0, const float* __restrict__ x0,
                const float* __restrict__ sigma0, const float* __restrict__ x1,
                const float* __restrict__ sigma1) {
    if (blockIdx.x == 0 && threadIdx.x < BB) {      // fused init
        int b = threadIdx.x;
        rodrigues(twist0[b*6+0], twist0[b*6+1], twist0[b*6+2], g_R[b]);
        g_t[b][0] = twist0[b*6+3];
        g_t[b][1] = twist0[b*6+4];
        g_t[b][2] = twist0[b*6+5];
#pragma unroll
        for (int k = 0; k < 27; k++) g_acc[b][k] = 0.0f;
    }

    int t = blockIdx.x * 256 + threadIdx.x;         // one thread = 4 pixels, one channel-pair
    int nPix4 = NN / 4;
    int p4  = (t % nPix4) * 4;
    int bp  = t / nPix4;                             // 0..BB*PAIRS-1
    int b    = bp >> 3;
    int pair = bp & 7;
    int v  = p4 / WW;
    int u0 = p4 - v*WW;                              // %4==0, row-contained

    int vm = max(v-1, 0)*WW, v0r = v*WW, vp = min(v+1, HH-1)*WW;
    int ul = max(u0-1, 0);
    int ur = min(u0+4, WW-1);

    float av[2][4], gv[2][4], x0a[2][4], s0a[2][4], x1a[2][4], s1a[2][4];
#pragma unroll
    for (int ch = 0; ch < 2; ch++) {
        int c = pair*2 + ch;
        size_t off = (size_t)(b*CC + c)*NN;
        const float* img = x0 + off;

        float top[6], mid[6], bot[6];
        float4 q;
        q = *(const float4*)(img + vm + u0);
        top[0]=img[vm+ul]; top[1]=q.x; top[2]=q.y; top[3]=q.z; top[4]=q.w; top[5]=img[vm+ur];
        q = *(const float4*)(img + v0r + u0);
        mid[0]=img[v0r+ul]; mid[1]=q.x; mid[2]=q.y; mid[3]=q.z; mid[4]=q.w; mid[5]=img[v0r+ur];
        q = *(const float4*)(img + vp + u0);
        bot[0]=img[vp+ul]; bot[1]=q.x; bot[2]=q.y; bot[3]=q.z; bot[4]=q.w; bot[5]=img[vp+ur];

        float4 s0v = *(const float4*)(sigma0 + off + p4);
        float4 xv  = *(const float4*)(x1 + off + p4);
        float4 sv  = *(const float4*)(sigma1 + off + p4);
        s0a[ch][0]=s0v.x; s0a[ch][1]=s0v.y; s0a[ch][2]=s0v.z; s0a[ch][3]=s0v.w;
        x1a[ch][0]=xv.x;  x1a[ch][1]=xv.y;  x1a[ch][2]=xv.z;  x1a[ch][3]=xv.w;
        s1a[ch][0]=sv.x;  s1a[ch][1]=sv.y;  s1a[ch][2]=sv.z;  s1a[ch][3]=sv.w;

#pragma unroll
        for (int i = 0; i < 4; i++) {
            float tl = top[i], tc_ = top[i+1], tr = top[i+2];
            float ml = mid[i],                 mr = mid[i+2];
            float bl = bot[i], bc_ = bot[i+1], br = bot[i+2];
            float dx = tr - tl + 2.0f*(mr - ml) + (br - bl);
            float dy = bl - tl + 2.0f*(bc_ - tc_) + (br - tr);
            float rinv = rsqrtf(dx*dx + dy*dy + 1e-8f);
            av[ch][i] = dx*rinv;
            gv[ch][i] = dy*rinv;
            x0a[ch][i] = mid[i+1];
        }
    }

    size_t plane = (size_t)bp*NN + p4;
    uint4* co = (uint4*)&g_cen4[plane];
#pragma unroll
    for (int h = 0; h < 2; h++) {
        int i0 = h*2, i1 = h*2 + 1;
        co[h] = make_uint4(
            pack_fp8x4(av[0][i0], av[1][i0], gv[0][i0], gv[1][i0]),
            pack_fp8x4(x0a[0][i0], x0a[1][i0], s0a[0][i0], s0a[1][i0]),
            pack_fp8x4(av[0][i1], av[1][i1], gv[0][i1], gv[1][i1]),
            pack_fp8x4(x0a[0][i1], x0a[1][i1], s0a[0][i1], s0a[1][i1]));
    }
    *(uint4*)&g_gath4[plane] = make_uint4(
        pack_fp8x4(x1a[0][0], x1a[1][0], s1a[0][0], s1a[1][0]),
        pack_fp8x4(x1a[0][1], x1a[1][1], s1a[0][1], s1a[1][1]),
        pack_fp8x4(x1a[0][2], x1a[1][2], s1a[0][2], s1a[1][2]),
        pack_fp8x4(x1a[0][3], x1a[1][3], s1a[0][3], s1a[1][3]));
}

// ---------------- fused per-iteration accumulation + last-block solve ----------------
__global__ __launch_bounds__(256, 4)
void iterKernel(const float* __restrict__ invD0, const float* __restrict__ invD1,
                const float* __restrict__ Kmat, float* __restrict__ out, int last)
{
    const int b  = blockIdx.y;
    const int p2 = (blockIdx.x * 256 + threadIdx.x) * 2;

    __shared__ float sm[27][8];
    int lane = threadIdx.x & 31;
    int warp = threadIdx.x >> 5;

    {
        const float fx = Kmat[b*4+0], fy = Kmat[b*4+1];
        const float cx = Kmat[b*4+2], cy = Kmat[b*4+3];
        const float ifx = 1.0f/fx, ify = 1.0f/fy;
        const float* Rb = g_R[b];
        const float* tb = g_t[b];

        int vpix = p2 / WW;
        int u0   = p2 - vpix*WW;
        float y  = ((float)vpix - cy) * ify;
        float2 d2 = *(const float2*)(invD0 + (size_t)b*NN + p2);
        float dd[2] = {d2.x, d2.y};

        float xs_[2], valid[2];
        __half2 w00h[2], w01h[2], w10h[2], w11h[2];
        int o00[2], o01[2], o10[2], o11[2];
        const float* D1 = invD1 + (size_t)b*NN;

#pragma unroll
        for (int i = 0; i < 2; i++) {
            float x = ((float)(u0 + i) - cx) * ifx;
            xs_[i] = x;
            float d = dd[i];
            float X = Rb[0]*x + Rb[1]*y + Rb[2] + tb[0]*d;
            float Y = Rb[3]*x + Rb[4]*y + Rb[5] + tb[1]*d;
            float S = Rb[6]*x + Rb[7]*y + Rb[8] + tb[2]*d;
            float invS = __fdividef(1.0f, S);
            float u = X * invS * fx + cx;
            float v = Y * invS * fy + cy;
            float invz = d * invS;

            float uc = fminf(fmaxf(u, 0.0f), (float)(WW-1));
            float vc = fminf(fmaxf(v, 0.0f), (float)(HH-1));
            float x0f = floorf(uc), y0f = floorf(vc);
            float wx = uc - x0f, wy = vc - y0f;
            int xi0 = (int)x0f, yi0 = (int)y0f;
            int xi1 = min(xi0 + 1, WW-1), yi1 = min(yi0 + 1, HH-1);
            float w00 = (1.0f-wx)*(1.0f-wy), w01 = wx*(1.0f-wy);
            float w10 = (1.0f-wx)*wy,        w11 = wx*wy;
            o00[i] = yi0*WW + xi0; o01[i] = yi0*WW + xi1;
            o10[i] = yi1*WW + xi0; o11[i] = yi1*WW + xi1;
            w00h[i] = __float2half2_rn(w00); w01h[i] = __float2half2_rn(w01);
            w10h[i] = __float2half2_rn(w10); w11h[i] = __float2half2_rn(w11);

            float dz = D1[o00[i]]*w00 + D1[o01[i]]*w01 + D1[o10[i]]*w10 + D1[o11[i]]*w11;
            bool inlier = invz > dz - 0.1f;
            bool inview = (u > 0.0f) && (u < (float)WW) && (v > 0.0f) && (v < (float)HH);
            valid[i] = (inlier && inview) ? 1.0f : 0.0f;
        }

        // half2 S-accumulators (lanes = channels of a pair), per pixel
        __half2 Saah[2], Sabh[2], Sbbh[2], Sarh[2], Sbrh[2];
#pragma unroll
        for (int i = 0; i < 2; i++) {
            Saah[i] = __float2half2_rn(0.0f); Sabh[i] = Saah[i]; Sbbh[i] = Saah[i];
            Sarh[i] = Saah[i]; Sbrh[i] = Saah[i];
        }

#pragma unroll
        for (int pair = 0; pair < PAIRS; pair++) {
            size_t plane = (size_t)(b*PAIRS + pair)*NN;
            uint4 cvq = __ldg((const uint4*)&g_cen4[plane + p2]);  // 2 px × uint2
            const unsigned* G = g_gath4 + plane;
            unsigned cenA[2] = {cvq.x, cvq.z};   // {a,g} words
            unsigned cenB[2] = {cvq.y, cvq.w};   // {x0,s0} words
#pragma unroll
            for (int i = 0; i < 2; i++) {
                unsigned q00 = __ldg(G + o00[i]);
                unsigned q01 = __ldg(G + o01[i]);
                unsigned q10 = __ldg(G + o10[i]);
                unsigned q11 = __ldg(G + o11[i]);
                // bilinear x1 (lanes=channels)
                __half2 frh = __hmul2(fp8x2_to_h2((unsigned short)(q00 & 0xFFFFu)), w00h[i]);
                frh = __hfma2(fp8x2_to_h2((unsigned short)(q01 & 0xFFFFu)), w01h[i], frh);
                frh = __hfma2(fp8x2_to_h2((unsigned short)(q10 & 0xFFFFu)), w10h[i], frh);
                frh = __hfma2(fp8x2_to_h2((unsigned short)(q11 & 0xFFFFu)), w11h[i], frh);
                // bilinear sigma1
                __half2 srh = __hmul2(fp8x2_to_h2((unsigned short)(q00 >> 16)), w00h[i]);
                srh = __hfma2(fp8x2_to_h2((unsigned short)(q01 >> 16)), w01h[i], srh);
                srh = __hfma2(fp8x2_to_h2((unsigned short)(q10 >> 16)), w10h[i], srh);
                srh = __hfma2(fp8x2_to_h2((unsigned short)(q11 >> 16)), w11h[i], srh);

                __half2 ha  = fp8x2_to_h2((unsigned short)(cenA[i] & 0xFFFFu));
                __half2 hg  = fp8x2_to_h2((unsigned short)(cenA[i] >> 16));
                __half2 hx0 = fp8x2_to_h2((unsigned short)(cenB[i] & 0xFFFFu));
                __half2 hs0 = fp8x2_to_h2((unsigned short)(cenB[i] >> 16));

                __half2 s2h  = __hfma2(srh, srh, __hmul2(hs0, hs0));
                __half2 wgth = h2rcp(s2h);
                __half2 resh = __hsub2(frh, hx0);
                __half2 awh  = __hmul2(ha, wgth);
                __half2 gwh  = __hmul2(hg, wgth);
                Saah[i] = __hfma2(awh, ha,   Saah[i]);
                Sabh[i] = __hfma2(awh, hg,   Sabh[i]);
                Sbbh[i] = __hfma2(gwh, hg,   Sbbh[i]);
                Sarh[i] = __hfma2(awh, resh, Sarh[i]);
                Sbrh[i] = __hfma2(gwh, resh, Sbrh[i]);
            }
        }

        // per-pixel horizontal sums + factorized vectors (both pixels live)
        float Jx0[6], Jy0[6], Jx1[6], Jy1[6];
        float uu0[6], vv0[6], uu1[6], vv1[6];
        float Sar0, Sbr0, Sar1, Sbr1;
        {
            float2 t;
#pragma unroll
            for (int i = 0; i < 2; i++) {
                t = __half22float2(Saah[i]); float Saa = (t.x + t.y) * valid[i];
                t = __half22float2(Sabh[i]); float Sab = (t.x + t.y) * valid[i];
                t = __half22float2(Sbbh[i]); float Sbb = (t.x + t.y) * valid[i];
                t = __half22float2(Sarh[i]); float Sar = (t.x + t.y) * valid[i];
                t = __half22float2(Sbrh[i]); float Sbr = (t.x + t.y) * valid[i];

                float x = xs_[i], d = dd[i];
                float xy = x*y;
                float* Jx = (i == 0) ? Jx0 : Jx1;
                float* Jy = (i == 0) ? Jy0 : Jy1;
                Jx[0] = -xy*fx;          Jx[1] = (1.0f + x*x)*fx; Jx[2] = -y*fx;
                Jx[3] = d*fx;            Jx[4] = 0.0f;            Jx[5] = -d*x*fx;
                Jy[0] = -(1.0f+y*y)*fy;  Jy[1] = xy*fy;           Jy[2] = x*fy;
                Jy[3] = 0.0f;            Jy[4] = d*fy;            Jy[5] = -d*y*fy;

                float* uu = (i == 0) ? uu0 : uu1;
                float* vv = (i == 0) ? vv0 : vv1;
#pragma unroll
                for (int k = 0; k < 6; k++) {
                    uu[k] = Saa*Jx[k] + Sab*Jy[k];
                    vv[k] = Sab*Jx[k] + Sbb*Jy[k];
                }
                if (i == 0) { Sar0 = Sar; Sbr0 = Sbr; } else { Sar1 = Sar; Sbr1 = Sbr; }
            }
        }

        // ---- sequential expand + immediate warp-reduce (no acc[27] array) ----
        int idx = 0;
#pragma unroll
        for (int k = 0; k < 6; k++) {
#pragma unroll
            for (int l = k; l < 6; l++) {
                float aval = uu0[k]*Jx0[l] + vv0[k]*Jy0[l]
                           + uu1[k]*Jx1[l] + vv1[k]*Jy1[l];
#pragma unroll
                for (int off = 16; off > 0; off >>= 1)
                    aval += __shfl_down_sync(0xFFFFFFFFu, aval, off);
                if (lane == 0) sm[idx][warp] = aval;
                idx++;
            }
        }
#pragma unroll
        for (int k = 0; k < 6; k++) {
            float aval = Sar0*Jx0[k] + Sbr0*Jy0[k] + Sar1*Jx1[k] + Sbr1*Jy1[k];
#pragma unroll
            for (int off = 16; off > 0; off >>= 1)
                aval += __shfl_down_sync(0xFFFFFFFFu, aval, off);
            if (lane == 0) sm[21+k][warp] = aval;
        }
    }

    __syncthreads();
    if (threadIdx.x < 27) {
        float s = 0.0f;
#pragma unroll
        for (int w = 0; w < 8; w++) s += sm[threadIdx.x][w];
        // RETURNING atomic: consuming 'old' forces the RMW to complete at L2
        // (device point of coherence) before this thread reaches the barrier.
        // Avoids __threadfence() (CCTL.IVALL = full L1D flush).
        float old = atomicAdd(&g_acc[blockIdx.y][threadIdx.x], s);
        if (__float_as_uint(old) == 0x7f800123u) sm[0][0] = old;  // consume (never taken)
    }
    __syncthreads();

    // ---- last-block-does-solve ----
    __shared__ bool sLast;
    if (threadIdx.x == 0) {
        unsigned int done = atomicAdd(&g_count, 1u);
        sLast = (done == ITER_BLOCKS - 1);
    }
    __syncthreads();
    if (!sLast) return;
    if (threadIdx.x == 0) g_count = 0;

    if (threadIdx.x < BB) {
        int bb = threadIdx.x;
        float M[6][7];
        {
            float Jt[6][6];
            int idx = 0;
#pragma unroll
            for (int k = 0; k < 6; k++)
#pragma unroll
                for (int l = k; l < 6; l++) {
                    float vvv = __ldcg(&g_acc[bb][idx]);  // L2 read, bypass L1
                    idx++;
                    Jt[k][l] = vvv; Jt[l][k] = vvv;
                }
            float tr = 0.0f;
#pragma unroll
            for (int k = 0; k < 6; k++) tr += Jt[k][k];
            float lam = tr * 1e-6f;
#pragma unroll
            for (int i = 0; i < 6; i++) {
#pragma unroll
                for (int j = 0; j < 6; j++) M[i][j] = Jt[i][j] + (i == j ? lam : 0.0f);
                M[i][6] = __ldcg(&g_acc[bb][21+i]);
            }
        }
        for (int k = 0; k < 6; k++) {
            int piv = k; float mx = fabsf(M[k][k]);
            for (int i = k+1; i < 6; i++) {
                float a = fabsf(M[i][k]);
                if (a > mx) { mx = a; piv = i; }
            }
            if (piv != k)
                for (int j = k; j < 7; j++) { float tmp = M[k][j]; M[k][j] = M[piv][j]; M[piv][j] = tmp; }
            float inv = 1.0f / M[k][k];
            for (int i = k+1; i < 6; i++) {
                float f = M[i][k] * inv;
                for (int j = k; j < 7; j++) M[i][j] -= f * M[k][j];
            }
        }
        float xi[6];
        for (int i = 5; i >= 0; i--) {
            float s = M[i][6];
            for (int j = i+1; j < 6; j++) s -= M[i][j] * xi[j];
            xi[i] = s / M[i][i];
        }

        float dR[9];
        rodrigues(-xi[0], -xi[1], -xi[2], dR);
        float dt[3];
        dt[0] = -(dR[0]*xi[3] + dR[1]*xi[4] + dR[2]*xi[5]);
        dt[1] = -(dR[3]*xi[3] + dR[4]*xi[4] + dR[5]*xi[5]);
        dt[2] = -(dR[6]*xi[3] + dR[7]*xi[4] + dR[8]*xi[5]);

        float Rb[9], tb[3];
#pragma unroll
        for (int i = 0; i < 9; i++) Rb[i] = g_R[bb][i];
#pragma unroll
        for (int i = 0; i < 3; i++) tb[i] = g_t[bb][i];

        float nt[3], nR[9];
#pragma unroll
        for (int i = 0; i < 3; i++)
            nt[i] = Rb[i*3+0]*dt[0] + Rb[i*3+1]*dt[1] + Rb[i*3+2]*dt[2] + tb[i];
#pragma unroll
        for (int i = 0; i < 3; i++)
#pragma unroll
            for (int j = 0; j < 3; j++)
                nR[i*3+j] = Rb[i*3+0]*dR[0*3+j] + Rb[i*3+1]*dR[1*3+j] + Rb[i*3+2]*dR[2*3+j];

#pragma unroll
        for (int i = 0; i < 9; i++) g_R[bb][i] = nR[i];
#pragma unroll
        for (int i = 0; i < 3; i++) g_t[bb][i] = nt[i];
#pragma unroll
        for (int k = 0; k < 27; k++) g_acc[bb][k] = 0.0f;

        if (last) {
#pragma unroll
            for (int i = 0; i < 9; i++) out[bb*12 + i] = nR[i];
#pragma unroll
            for (int i = 0; i < 3; i++) out[bb*12 + 9 + i] = nt[i];
        }
    }
}

// ---------------- launch ----------------
extern "C" void kernel_launch(void* const* d_in, const int* in_sizes, int n_in,
                              void* d_out, int out_size) {
    const float* twist0 = (const float*)d_in[0];
    const float* x0     = (const float*)d_in[1];
    const float* x1     = (const float*)d_in[2];
    const float* invD0  = (const float*)d_in[3];
    const float* invD1  = (const float*)d_in[4];
    const float* sigma0 = (const float*)d_in[5];
    const float* sigma1 = (const float*)d_in[6];
    const float* Kmat   = (const float*)d_in[7];
    float* out = (float*)d_out;

    packKernel<<<BB*PAIRS*(NN/4)/256, 256>>>(twist0, x0, sigma0, x1, sigma1);
    for (int it = 0; it < 3; ++it) {
        dim3 grid(NN/2/256, BB);
        iterKernel<<<grid, 256>>>(invD0, invD1, Kmat, out, it == 2);
    }
}